// round 15
// baseline (speedup 1.0000x reference)
#include <cuda_runtime.h>
#include <cuda_bf16.h>
#include <math.h>
#include <stdint.h>

#define BSZ   8192
#define TT    2
#define NF    40
#define DD    64
#define FEPS  1e-5f
#define CHUNK 4

typedef unsigned long long u64;

// ---- split-bf16: (a,b) -> hi pair + residual pair ----
__device__ __forceinline__ void splitpk(float a, float b, uint32_t& hi, uint32_t& lo) {
    __nv_bfloat162 h = __floats2bfloat162_rn(a, b);
    float ra = a - __bfloat162float(h.x);
    float rb = b - __bfloat162float(h.y);
    __nv_bfloat162 l = __floats2bfloat162_rn(ra, rb);
    hi = *reinterpret_cast<uint32_t*>(&h);
    lo = *reinterpret_cast<uint32_t*>(&l);
}
__device__ __forceinline__ float2 rec2(uint32_t h, uint32_t l) {
    float2 hf = __bfloat1622float2(*reinterpret_cast<__nv_bfloat162*>(&h));
    float2 lf = __bfloat1622float2(*reinterpret_cast<__nv_bfloat162*>(&l));
    return make_float2(hf.x + lf.x, hf.y + lf.y);
}

// ---- legacy tensor core mma (sm_80+) ----
__device__ __forceinline__ void mma_bf16(float* d,
    uint32_t a0, uint32_t a1, uint32_t a2, uint32_t a3,
    uint32_t b0, uint32_t b1) {
    asm volatile(
        "mma.sync.aligned.m16n8k16.row.col.f32.bf16.bf16.f32 "
        "{%0,%1,%2,%3}, {%4,%5,%6,%7}, {%8,%9}, {%0,%1,%2,%3};"
        : "+f"(d[0]), "+f"(d[1]), "+f"(d[2]), "+f"(d[3])
        : "r"(a0), "r"(a1), "r"(a2), "r"(a3), "r"(b0), "r"(b1));
}

// ---- ldmatrix x4 (sm_75+) ----
__device__ __forceinline__ void ldsm4(uint32_t& r0, uint32_t& r1,
                                      uint32_t& r2, uint32_t& r3, uint32_t addr) {
    asm volatile("ldmatrix.sync.aligned.m8n8.x4.shared.b16 {%0,%1,%2,%3}, [%4];"
        : "=r"(r0), "=r"(r1), "=r"(r2), "=r"(r3) : "r"(addr));
}

// ---- cp.async (sm_80+) ----
__device__ __forceinline__ uint32_t smem_u32(const void* p) {
    uint32_t a;
    asm("{ .reg .u64 t; cvta.to.shared.u64 t, %1; cvt.u32.u64 %0, t; }" : "=r"(a) : "l"(p));
    return a;
}
__device__ __forceinline__ void cpa16(uint32_t dst, const void* src) {
    asm volatile("cp.async.cg.shared.global [%0], [%1], 16;" :: "r"(dst), "l"(src));
}
#define CPA_COMMIT() asm volatile("cp.async.commit_group;" ::: "memory")
#define CPA_WAIT(n)  asm volatile("cp.async.wait_group %0;" :: "n"(n) : "memory")

// ---------------- device scratch ----------------
__device__ float g_S [TT*NF*128];
__device__ float g_BP[TT*NF*DD];
__device__ uint32_t g_WPH[TT*64*64];
__device__ uint32_t g_WPL[TT*64*64];
__device__ uint32_t g_APH[TT*48*24];
__device__ uint32_t g_APL[TT*48*24];
__device__ uint32_t g_HH[(size_t)BSZ*TT*1280];
__device__ uint32_t g_HL[(size_t)BSZ*TT*1280];
__device__ uint32_t g_GPH[NF*1280];
__device__ uint32_t g_GPL[NF*1280];

// ---------------- prep 1: adj -> LN -> mask -> softmax -> A^T split pairs --
__global__ void prep_adj(const float* __restrict__ masker,
                         const float* __restrict__ ln_gamma,
                         const float* __restrict__ ln_beta) {
    int t = blockIdx.x;
    __shared__ float sadj[NF*NF];
    int tid = threadIdx.x;
    const float* mk = masker + (size_t)t * 3 * NF * NF;
    for (int i = tid; i < NF*NF; i += blockDim.x) {
        float p = mk[i] * mk[NF*NF + i] * mk[2*NF*NF + i];
        sadj[i] = p > 0.f ? p : 0.f;
    }
    __syncthreads();
    if (tid < NF) {
        int j = tid;
        float sum = 0.f, sq = 0.f;
        for (int i = 0; i < NF; ++i) { float a = sadj[i*NF + j]; sum += a; sq += a*a; }
        float mu  = sum * (1.f/NF);
        float var = sq * (1.f/NF) - mu*mu;
        float rs  = rsqrtf(var + FEPS);
        float xm[NF];
        float mx = -1e30f;
        for (int i = 0; i < NF; ++i) {
            float a   = sadj[i*NF + j];
            float msk = (a != 0.f) ? 1.f : 0.f;
            float v   = (a - mu) * rs * ln_gamma[i] + ln_beta[i];
            v += (1.f - msk) * (-1e9f);
            if (i == j) v += 1.f;
            xm[i] = v;
            mx = fmaxf(mx, v);
        }
        float se = 0.f;
        for (int i = 0; i < NF; ++i) { xm[i] = expf(xm[i] - mx); se += xm[i]; }
        float inv = 1.f / se;
        float av[NF];
        for (int i = 0; i < NF; ++i) {
            float a   = sadj[i*NF + j];
            float msk = (a != 0.f) ? 1.f : 0.f;
            av[i] = xm[i] * inv * msk;
        }
        #pragma unroll
        for (int p = 0; p < 20; ++p) {
            uint32_t hi, lo;
            splitpk(av[2*p], av[2*p+1], hi, lo);
            g_APH[t*1152 + j*24 + p] = hi;
            g_APL[t*1152 + j*24 + p] = lo;
        }
        #pragma unroll
        for (int p = 20; p < 24; ++p) {
            g_APH[t*1152 + j*24 + p] = 0u;
            g_APL[t*1152 + j*24 + p] = 0u;
        }
    } else if (tid >= 64 && tid < 72) {
        int n = 40 + (tid - 64);
        #pragma unroll
        for (int p = 0; p < 24; ++p) {
            g_APH[t*1152 + n*24 + p] = 0u;
            g_APL[t*1152 + n*24 + p] = 0u;
        }
    }
}

// ---------------- prep 2: sbp + wp + gp fused ----------------------------
__global__ void prep_misc(const float* __restrict__ bn_gamma,
                          const float* __restrict__ bn_beta,
                          const float* __restrict__ bn_mean,
                          const float* __restrict__ bn_var,
                          const float* __restrict__ gnn_w,
                          const float* __restrict__ gnn_b,
                          const float* __restrict__ gate_w) {
    int bid = blockIdx.x;
    int tid = threadIdx.x;
    if (bid < 80) {
        int t = bid / NF, n = bid - t*NF;
        __shared__ float so[128];
        if (tid < 128) {
            int F = bid*128 + tid;
            float s = bn_gamma[F] * rsqrtf(bn_var[F] + FEPS);
            float o = bn_beta[F] - bn_mean[F] * s;
            g_S[bid*128 + tid] = s;
            so[tid] = o;
        }
        __syncthreads();
        if (tid < DD) {
            float acc = gnn_b[t*NF*DD + n*DD + tid];
            #pragma unroll 8
            for (int f = 0; f < 128; ++f)
                acc += so[f] * gnn_w[t*128*DD + f*DD + tid];
            g_BP[bid*DD + tid] = acc;
        }
    } else if (bid < 112) {
        int i = (bid - 80)*256 + tid;
        if (i < TT*64*64) {
            int t = i >> 12, r = i & 4095;
            int p = r >> 6, d = r & 63;
            float w0 = gnn_w[t*8192 + (2*p)*64 + d];
            float w1 = gnn_w[t*8192 + (2*p+1)*64 + d];
            uint32_t hi, lo;
            splitpk(w0, w1, hi, lo);
            g_WPH[i] = hi;
            g_WPL[i] = lo;
        }
    } else {
        int i = (bid - 112)*256 + tid;
        if (i < NF*1280) {
            int c = i / 1280, p = i - c*1280;
            float w0 = gate_w[(2*p)*NF + c];
            float w1 = gate_w[(2*p+1)*NF + c];
            uint32_t hi, lo;
            splitpk(w0, w1, hi, lo);
            g_GPH[i] = hi;
            g_GPL[i] = lo;
        }
    }
}

// ---------------- kernel 1: split-bf16 MMA forward, CHUNK=4 --------------
// smem (u32 words):
//  sXPH [24][264] @0      sXPL @6336       (x pairs, K=m, cols c*64+d, c<4)
//  sATH [48][28]  @12672  sATL @14016
//  sCPH [160][68] @15360  sCPL @26240
//  sWPH [64][68]  @37120  sWPL @41472
// total 45824 words = 183296 B -> 1 CTA/SM
#define XSTR 264
#define SMF_XPH 0
#define SMF_XPL 6336
#define SMF_ATH 12672
#define SMF_ATL 14016
#define SMF_CPH 15360
#define SMF_CPL 26240
#define SMF_WPH 37120
#define SMF_WPL 41472
#define SMF_WORDS 45824
#define SM_FWD_BYTES (SMF_WORDS*4)
__global__ __launch_bounds__(256, 1)
void k_forward(const float* __restrict__ x) {
    extern __shared__ uint32_t sw[];
    uint32_t* sXPH = sw + SMF_XPH;
    uint32_t* sXPL = sw + SMF_XPL;
    uint32_t* sATH = sw + SMF_ATH;
    uint32_t* sATL = sw + SMF_ATL;
    uint32_t* sCPH = sw + SMF_CPH;
    uint32_t* sCPL = sw + SMF_CPL;
    uint32_t* sWPH = sw + SMF_WPH;
    uint32_t* sWPL = sw + SMF_WPL;
    uint32_t sbase = smem_u32(sw);

    int tid  = threadIdx.x;
    int wid  = tid >> 5, lane = tid & 31;
    int g    = lane >> 2, tg = lane & 3;
    uint32_t lrow = lane & 15;
    uint32_t lcol = (lane >> 4) << 2;
    int b0   = blockIdx.x * CHUNK;
    const float* xb = x + (size_t)b0 * NF * DD;

    // ---- x pair tiles (t-invariant): XP[p=m/2][c*64+d], c<4 ----
    for (int idx = tid; idx < 5120; idx += 256) {
        int p   = idx >> 8;           // 0..19
        int col = idx & 255;
        int c = col >> 6, d = col & 63;
        float x0 = __ldg(xb + c*2560 + (2*p)*64 + d);
        float x1 = __ldg(xb + c*2560 + (2*p+1)*64 + d);
        uint32_t h, l;
        splitpk(x0, x1, h, l);
        sXPH[p*XSTR + col] = h;
        sXPL[p*XSTR + col] = l;
    }
    for (int idx = tid; idx < 4*XSTR; idx += 256) {
        sXPH[20*XSTR + idx] = 0u;
        sXPL[20*XSTR + idx] = 0u;
    }

    for (int t = 0; t < TT; ++t) {
        for (int idx = tid; idx < 1152; idx += 256) {
            int n = idx / 24, p = idx - n*24;
            sATH[n*28 + p] = g_APH[t*1152 + idx];
            sATL[n*28 + p] = g_APL[t*1152 + idx];
        }
        for (int idx = tid; idx < 1024; idx += 256) {
            int p = idx >> 4, dq = (idx & 15) * 4;
            *(uint4*)(sWPH + p*68 + dq) = *(const uint4*)(g_WPH + t*4096 + p*64 + dq);
            *(uint4*)(sWPL + p*68 + dq) = *(const uint4*)(g_WPL + t*4096 + p*64 + dq);
        }
        for (int idx = tid; idx < 2560; idx += 256) {
            int row = idx >> 4, q = idx & 15;
            int c = row / 40, n = row - c*40;
            float4 xv = __ldg((const float4*)(xb + c*2560 + n*64 + q*4));
            float4 sv = __ldg((const float4*)(g_S + t*NF*128 + n*128 + q*4));
            uint32_t h0, l0, h1, l1;
            splitpk(xv.x*sv.x, xv.y*sv.y, h0, l0);
            splitpk(xv.z*sv.z, xv.w*sv.w, h1, l1);
            *(uint2*)(sCPH + row*68 + q*2) = make_uint2(h0, h1);
            *(uint2*)(sCPL + row*68 + q*2) = make_uint2(l0, l1);
        }
        __syncthreads();

        // ---- phase A MMA: nei[48 x 256] = A^T[48x48] @ xp[48x256] ----
        {
            float ahh[3][4][4], axx[3][4][4];
            #pragma unroll
            for (int m = 0; m < 3; ++m)
                #pragma unroll
                for (int c2 = 0; c2 < 4; ++c2)
                    #pragma unroll
                    for (int j = 0; j < 4; ++j) { ahh[m][c2][j] = 0.f; axx[m][c2][j] = 0.f; }

            #pragma unroll
            for (int ks = 0; ks < 3; ++ks) {
                uint32_t bh0[4], bh1[4], bl0[4], bl1[4];
                #pragma unroll
                for (int c2 = 0; c2 < 4; ++c2) {
                    int colb = (wid*4 + c2)*8 + g;
                    bh0[c2] = sXPH[(ks*8 + tg)*XSTR + colb];
                    bh1[c2] = sXPH[(ks*8 + tg + 4)*XSTR + colb];
                    bl0[c2] = sXPL[(ks*8 + tg)*XSTR + colb];
                    bl1[c2] = sXPL[(ks*8 + tg + 4)*XSTR + colb];
                }
                #pragma unroll
                for (int mt = 0; mt < 3; ++mt) {
                    uint32_t ah = sbase + (SMF_ATH + (mt*16 + lrow)*28 + ks*8 + lcol)*4u;
                    uint32_t a0h, a1h, a2h, a3h, a0l, a1l, a2l, a3l;
                    ldsm4(a0h, a1h, a2h, a3h, ah);
                    ldsm4(a0l, a1l, a2l, a3l, ah + (SMF_ATL - SMF_ATH)*4u);
                    #pragma unroll
                    for (int c2 = 0; c2 < 4; ++c2) {
                        mma_bf16(ahh[mt][c2], a0h, a1h, a2h, a3h, bh0[c2], bh1[c2]);
                        mma_bf16(axx[mt][c2], a0h, a1h, a2h, a3h, bl0[c2], bl1[c2]);
                        mma_bf16(axx[mt][c2], a0l, a1l, a2l, a3l, bh0[c2], bh1[c2]);
                    }
                }
            }

            // epilogue A: scale by s_hi, split, write cat upper half
            #pragma unroll
            for (int mt = 0; mt < 3; ++mt) {
                #pragma unroll
                for (int c2 = 0; c2 < 4; ++c2) {
                    int col = (wid*4 + c2)*8 + tg*2;
                    int c = col >> 6, d = col & 63;
                    int r0 = mt*16 + g;
                    if (r0 < NF) {
                        float2 sv = *(const float2*)(g_S + t*NF*128 + r0*128 + 64 + d);
                        uint32_t h, l;
                        splitpk((ahh[mt][c2][0]+axx[mt][c2][0])*sv.x,
                                (ahh[mt][c2][1]+axx[mt][c2][1])*sv.y, h, l);
                        sCPH[(c*40 + r0)*68 + 32 + (d>>1)] = h;
                        sCPL[(c*40 + r0)*68 + 32 + (d>>1)] = l;
                    }
                    int r1 = mt*16 + 8 + g;
                    if (r1 < NF) {
                        float2 sv = *(const float2*)(g_S + t*NF*128 + r1*128 + 64 + d);
                        uint32_t h, l;
                        splitpk((ahh[mt][c2][2]+axx[mt][c2][2])*sv.x,
                                (ahh[mt][c2][3]+axx[mt][c2][3])*sv.y, h, l);
                        sCPH[(c*40 + r1)*68 + 32 + (d>>1)] = h;
                        sCPL[(c*40 + r1)*68 + 32 + (d>>1)] = l;
                    }
                }
            }
        }
        __syncthreads();

        // ---- phase B MMA: h[160x64] = cat[160x128] @ W[128x64] ----
        // warp = n8 column wid; loops all 10 m-tiles.
        {
            float hhacc[10][4], xxacc[10][4];
            #pragma unroll
            for (int m = 0; m < 10; ++m)
                #pragma unroll
                for (int j = 0; j < 4; ++j) { hhacc[m][j] = 0.f; xxacc[m][j] = 0.f; }

            #pragma unroll
            for (int s = 0; s < 8; ++s) {
                int pb0 = (8*s + tg)*68     + wid*8 + g;
                int pb1 = (8*s + tg + 4)*68 + wid*8 + g;
                uint32_t b0h = sWPH[pb0], b1h = sWPH[pb1];
                uint32_t b0l = sWPL[pb0], b1l = sWPL[pb1];
                #pragma unroll
                for (int m = 0; m < 10; ++m) {
                    uint32_t ah = sbase + (SMF_CPH + (m*16 + lrow)*68 + 8*s + lcol)*4u;
                    uint32_t a0h, a1h, a2h, a3h, a0l, a1l, a2l, a3l;
                    ldsm4(a0h, a1h, a2h, a3h, ah);
                    ldsm4(a0l, a1l, a2l, a3l, ah + (SMF_CPL - SMF_CPH)*4u);
                    mma_bf16(hhacc[m], a0h, a1h, a2h, a3h, b0h, b1h);
                    mma_bf16(xxacc[m], a0h, a1h, a2h, a3h, b0l, b1l);
                    mma_bf16(xxacc[m], a0l, a1l, a2l, a3l, b0h, b1h);
                }
            }

            int d = wid*8 + tg*2;
            int pq = wid*4 + tg;
            uint32_t hh[10][2], ll[10][2];
            #pragma unroll
            for (int m = 0; m < 10; ++m) {
                int r0 = m*16 + g, r1 = r0 + 8;
                int n0 = r0 - (r0/40)*40, n1 = r1 - (r1/40)*40;
                float2 bp0 = *(const float2*)(g_BP + t*2560 + n0*64 + d);
                float2 bp1 = *(const float2*)(g_BP + t*2560 + n1*64 + d);
                splitpk(hhacc[m][0] + xxacc[m][0] + bp0.x,
                        hhacc[m][1] + xxacc[m][1] + bp0.y, hh[m][0], ll[m][0]);
                splitpk(hhacc[m][2] + xxacc[m][2] + bp1.x,
                        hhacc[m][3] + xxacc[m][3] + bp1.y, hh[m][1], ll[m][1]);
            }
            __syncthreads();   // all warps done reading cat smem
            #pragma unroll
            for (int m = 0; m < 10; ++m) {
                int r0 = m*16 + g, r1 = r0 + 8;
                sCPH[r0*36 + pq] = hh[m][0];  sCPL[r0*36 + pq] = ll[m][0];
                sCPH[r1*36 + pq] = hh[m][1];  sCPL[r1*36 + pq] = ll[m][1];
            }
            __syncthreads();
            // coalesced copy: 160 rows x 8 uint4 per buffer
            for (int idx = tid; idx < 1280; idx += 256) {
                int r = idx >> 3, j = idx & 7;
                int c = r / 40, n = r - c*40;
                size_t dst = (size_t)((b0 + c)*TT + t) * 1280 + n*32 + j*4;
                *(uint4*)(g_HH + dst) = *(const uint4*)(sCPH + r*36 + j*4);
                *(uint4*)(g_HL + dst) = *(const uint4*)(sCPL + r*36 + j*4);
            }
        }
        __syncthreads();
    }
}

// ---------------- kernel 2: gate, 256 thr, ks-split on shared chunk ------
#define ASTR 36
#define AH_W (64*ASTR)
#define BH_W (NF*ASTR)
#define BUF_W (2*AH_W + 2*BH_W)
#define GSM_WORDS (3*BUF_W)
__device__ __forceinline__ void gate_issue_chunk_nc(uint32_t bufb, int row0, int ck, int tid) {
    #pragma unroll
    for (int q = 0; q < 2; ++q) {
        int idx = tid + q*256;
        int r = idx >> 3, j = idx & 7;
        uint32_t dst = bufb + (uint32_t)(r*ASTR + j*4)*4u;
        cpa16(dst, g_HH + (size_t)(row0 + r)*1280 + ck*32 + j*4);
        cpa16(dst + AH_W*4u, g_HL + (size_t)(row0 + r)*1280 + ck*32 + j*4);
    }
    #pragma unroll
    for (int q = 0; q < 2; ++q) {
        int idx = tid + q*256;
        if (idx < 320) {
            int c = idx >> 3, j = idx & 7;
            uint32_t dst = bufb + (uint32_t)(2*AH_W + c*ASTR + j*4)*4u;
            cpa16(dst, g_GPH + c*1280 + ck*32 + j*4);
            cpa16(dst + BH_W*4u, g_GPL + c*1280 + ck*32 + j*4);
        }
    }
}
__global__ __launch_bounds__(256, 2)
void k_gate(const float* __restrict__ gate_b, float* __restrict__ out) {
    extern __shared__ uint32_t gw[];
    uint32_t gb = smem_u32(gw);
    int tid  = threadIdx.x;
    int wid  = tid >> 5, lane = tid & 31;
    int kg   = wid >> 2;
    int mw   = wid & 3;
    int g    = lane >> 2, tg = lane & 3;
    uint32_t lrow = lane & 15;
    uint32_t lcol = (lane >> 4) << 2;
    int row0 = blockIdx.x * 64;

    float hhacc[5][4], xxacc[5][4];
    #pragma unroll
    for (int m = 0; m < 5; ++m)
        #pragma unroll
        for (int j = 0; j < 4; ++j) { hhacc[m][j] = 0.f; xxacc[m][j] = 0.f; }

    gate_issue_chunk_nc(gb, row0, 0, tid);
    CPA_COMMIT();
    gate_issue_chunk_nc(gb + (uint32_t)BUF_W*4u, row0, 1, tid);
    CPA_COMMIT();

    for (int ck = 0; ck < 40; ++ck) {
        if (ck + 1 < 40) { CPA_WAIT(1); } else { CPA_WAIT(0); }
        __syncthreads();

        int buf = ck % 3;
        const uint32_t* Bh = gw + buf*BUF_W + 2*AH_W;
        const uint32_t* Bl = Bh + BH_W;
        uint32_t abase = gb + (uint32_t)(buf*BUF_W)*4u;

        #pragma unroll
        for (int ks = 0; ks < 2; ++ks) {
            int ko = kg*16 + ks*8;
            uint32_t ah = abase + ((mw*16 + lrow)*ASTR + ko + lcol)*4u;
            uint32_t a0h, a1h, a2h, a3h, a0l, a1l, a2l, a3l;
            ldsm4(a0h, a1h, a2h, a3h, ah);
            ldsm4(a0l, a1l, a2l, a3l, ah + AH_W*4u);
            #pragma unroll
            for (int nt = 0; nt < 5; ++nt) {
                int pb = (nt*8 + g)*ASTR + ko + tg;
                uint32_t b0h = Bh[pb], b1h = Bh[pb+4];
                uint32_t b0l = Bl[pb], b1l = Bl[pb+4];
                mma_bf16(hhacc[nt], a0h, a1h, a2h, a3h, b0h, b1h);
                mma_bf16(xxacc[nt], a0h, a1h, a2h, a3h, b0l, b1l);
                mma_bf16(xxacc[nt], a0l, a1l, a2l, a3l, b0h, b1h);
            }
        }
        __syncthreads();
        if (ck + 2 < 40) {
            gate_issue_chunk_nc(gb + (uint32_t)(((ck + 2) % 3) * BUF_W)*4u, row0, ck + 2, tid);
            CPA_COMMIT();
        }
    }

    float acc[5][4];
    #pragma unroll
    for (int m = 0; m < 5; ++m)
        #pragma unroll
        for (int j = 0; j < 4; ++j) acc[m][j] = hhacc[m][j] + xxacc[m][j];

    float* sRed = (float*)gw;
    if (kg == 1) {
        int base = (tid - 128) * 20;
        #pragma unroll
        for (int m = 0; m < 5; ++m)
            #pragma unroll
            for (int j = 0; j < 4; ++j) sRed[base + m*4 + j] = acc[m][j];
    }
    __syncthreads();
    if (kg == 0) {
        int base = tid * 20;
        #pragma unroll
        for (int m = 0; m < 5; ++m)
            #pragma unroll
            for (int j = 0; j < 4; ++j) acc[m][j] += sRed[base + m*4 + j];
    }
    __syncthreads();

    float* sL = (float*)(gw + 4096);
    if (kg == 0) {
        #pragma unroll
        for (int nt = 0; nt < 5; ++nt) {
            int col = nt*8 + tg*2;
            float b0 = __ldg(gate_b + col);
            float b1 = __ldg(gate_b + col + 1);
            sL[(mw*16 + g)*41 + col]         = acc[nt][0] + b0;
            sL[(mw*16 + g)*41 + col + 1]     = acc[nt][1] + b1;
            sL[(mw*16 + 8 + g)*41 + col]     = acc[nt][2] + b0;
            sL[(mw*16 + 8 + g)*41 + col + 1] = acc[nt][3] + b1;
        }
    }
    __syncthreads();

    if (tid < 64) {
        float* lp = sL + tid*41;
        float mx = -1e30f;
        #pragma unroll 8
        for (int n = 0; n < NF; ++n) mx = fmaxf(mx, lp[n]);
        float se = 0.f;
        #pragma unroll 8
        for (int n = 0; n < NF; ++n) se += expf(lp[n] - mx);
        float inv = 1.f / se;
        #pragma unroll 8
        for (int n = 0; n < NF; ++n) lp[n] = expf(lp[n] - mx) * inv;
    }
    __syncthreads();

    {
        int row = tid >> 2;
        int q   = tid & 3;
        int pb  = q * 8;
        const uint32_t* hh = g_HH + (size_t)(row0 + row)*1280 + pb;
        const uint32_t* hl = g_HL + (size_t)(row0 + row)*1280 + pb;
        const float* wp = sL + row*41;
        float2 a2[8];
        #pragma unroll
        for (int k = 0; k < 8; ++k) a2[k] = make_float2(0.f, 0.f);
        #pragma unroll 4
        for (int n = 0; n < NF; ++n) {
            float wv = wp[n];
            #pragma unroll
            for (int q4 = 0; q4 < 2; ++q4) {
                uint4 hv = *(const uint4*)(hh + n*32 + q4*4);
                uint4 lv = *(const uint4*)(hl + n*32 + q4*4);
                float2 f0 = rec2(hv.x, lv.x), f1 = rec2(hv.y, lv.y);
                float2 f2 = rec2(hv.z, lv.z), f3 = rec2(hv.w, lv.w);
                a2[q4*4+0].x += wv*f0.x; a2[q4*4+0].y += wv*f0.y;
                a2[q4*4+1].x += wv*f1.x; a2[q4*4+1].y += wv*f1.y;
                a2[q4*4+2].x += wv*f2.x; a2[q4*4+2].y += wv*f2.y;
                a2[q4*4+3].x += wv*f3.x; a2[q4*4+3].y += wv*f3.y;
            }
        }
        float* op = out + (size_t)(row0 + row)*64 + q*16;
        #pragma unroll
        for (int k = 0; k < 4; ++k)
            *(float4*)(op + k*4) = make_float4(a2[k*2].x, a2[k*2].y, a2[k*2+1].x, a2[k*2+1].y);
    }
}

// ---------------- launcher ------------------------------------------------
extern "C" void kernel_launch(void* const* d_in, const int* in_sizes, int n_in,
                              void* d_out, int out_size) {
    const float* x        = (const float*)d_in[0];
    const float* masker   = (const float*)d_in[1];
    const float* ln_gamma = (const float*)d_in[2];
    const float* ln_beta  = (const float*)d_in[3];
    const float* gnn_w    = (const float*)d_in[4];
    const float* gnn_b    = (const float*)d_in[5];
    const float* bn_gamma = (const float*)d_in[6];
    const float* bn_beta  = (const float*)d_in[7];
    const float* bn_mean  = (const float*)d_in[8];
    const float* bn_var   = (const float*)d_in[9];
    const float* gate_w   = (const float*)d_in[10];
    const float* gate_b   = (const float*)d_in[11];
    float* out = (float*)d_out;

    cudaFuncSetAttribute(k_forward, cudaFuncAttributeMaxDynamicSharedMemorySize,
                         SM_FWD_BYTES);
    cudaFuncSetAttribute(k_gate, cudaFuncAttributeMaxDynamicSharedMemorySize,
                         GSM_WORDS * (int)sizeof(uint32_t));

    prep_adj<<<2, 128>>>(masker, ln_gamma, ln_beta);
    prep_misc<<<312, 256>>>(bn_gamma, bn_beta, bn_mean, bn_var, gnn_w, gnn_b, gate_w);
    k_forward<<<BSZ / CHUNK, 256, SM_FWD_BYTES>>>(x);
    k_gate<<<BSZ * TT / 64, 256, GSM_WORDS * sizeof(uint32_t)>>>(gate_b, out);
}

// round 16
// speedup vs baseline: 1.1753x; 1.1753x over previous
#include <cuda_runtime.h>
#include <cuda_bf16.h>
#include <math.h>
#include <stdint.h>

#define BSZ   8192
#define TT    2
#define NF    40
#define DD    64
#define FEPS  1e-5f
#define CHUNK 2

typedef unsigned long long u64;

// ---- split-bf16: (a,b) -> hi pair + residual pair ----
__device__ __forceinline__ void splitpk(float a, float b, uint32_t& hi, uint32_t& lo) {
    __nv_bfloat162 h = __floats2bfloat162_rn(a, b);
    float ra = a - __bfloat162float(h.x);
    float rb = b - __bfloat162float(h.y);
    __nv_bfloat162 l = __floats2bfloat162_rn(ra, rb);
    hi = *reinterpret_cast<uint32_t*>(&h);
    lo = *reinterpret_cast<uint32_t*>(&l);
}
__device__ __forceinline__ float2 rec2(uint32_t h, uint32_t l) {
    float2 hf = __bfloat1622float2(*reinterpret_cast<__nv_bfloat162*>(&h));
    float2 lf = __bfloat1622float2(*reinterpret_cast<__nv_bfloat162*>(&l));
    return make_float2(hf.x + lf.x, hf.y + lf.y);
}

// ---- legacy tensor core mma (sm_80+) ----
__device__ __forceinline__ void mma_bf16(float* d,
    uint32_t a0, uint32_t a1, uint32_t a2, uint32_t a3,
    uint32_t b0, uint32_t b1) {
    asm volatile(
        "mma.sync.aligned.m16n8k16.row.col.f32.bf16.bf16.f32 "
        "{%0,%1,%2,%3}, {%4,%5,%6,%7}, {%8,%9}, {%0,%1,%2,%3};"
        : "+f"(d[0]), "+f"(d[1]), "+f"(d[2]), "+f"(d[3])
        : "r"(a0), "r"(a1), "r"(a2), "r"(a3), "r"(b0), "r"(b1));
}

// ---- ldmatrix x4 (sm_75+) ----
__device__ __forceinline__ void ldsm4(uint32_t& r0, uint32_t& r1,
                                      uint32_t& r2, uint32_t& r3, uint32_t addr) {
    asm volatile("ldmatrix.sync.aligned.m8n8.x4.shared.b16 {%0,%1,%2,%3}, [%4];"
        : "=r"(r0), "=r"(r1), "=r"(r2), "=r"(r3) : "r"(addr));
}

// ---- cp.async (sm_80+) ----
__device__ __forceinline__ uint32_t smem_u32(const void* p) {
    uint32_t a;
    asm("{ .reg .u64 t; cvta.to.shared.u64 t, %1; cvt.u32.u64 %0, t; }" : "=r"(a) : "l"(p));
    return a;
}
__device__ __forceinline__ void cpa16(uint32_t dst, const void* src) {
    asm volatile("cp.async.cg.shared.global [%0], [%1], 16;" :: "r"(dst), "l"(src));
}
#define CPA_COMMIT() asm volatile("cp.async.commit_group;" ::: "memory")
#define CPA_WAIT(n)  asm volatile("cp.async.wait_group %0;" :: "n"(n) : "memory")

// ---------------- device scratch ----------------
__device__ float g_S [TT*NF*128];
__device__ float g_BP[TT*NF*DD];
__device__ uint32_t g_WPH[TT*64*64];
__device__ uint32_t g_WPL[TT*64*64];
__device__ uint32_t g_APH[TT*48*24];
__device__ uint32_t g_APL[TT*48*24];
__device__ uint32_t g_HH[(size_t)BSZ*TT*1280];
__device__ uint32_t g_HL[(size_t)BSZ*TT*1280];
__device__ uint32_t g_GPH[NF*1280];
__device__ uint32_t g_GPL[NF*1280];

// ---------------- prep 1: adj -> LN -> mask -> softmax -> A^T split pairs --
__global__ void prep_adj(const float* __restrict__ masker,
                         const float* __restrict__ ln_gamma,
                         const float* __restrict__ ln_beta) {
    int t = blockIdx.x;
    __shared__ float sadj[NF*NF];
    int tid = threadIdx.x;
    const float* mk = masker + (size_t)t * 3 * NF * NF;
    for (int i = tid; i < NF*NF; i += blockDim.x) {
        float p = mk[i] * mk[NF*NF + i] * mk[2*NF*NF + i];
        sadj[i] = p > 0.f ? p : 0.f;
    }
    __syncthreads();
    if (tid < NF) {
        int j = tid;
        float sum = 0.f, sq = 0.f;
        for (int i = 0; i < NF; ++i) { float a = sadj[i*NF + j]; sum += a; sq += a*a; }
        float mu  = sum * (1.f/NF);
        float var = sq * (1.f/NF) - mu*mu;
        float rs  = rsqrtf(var + FEPS);
        float xm[NF];
        float mx = -1e30f;
        for (int i = 0; i < NF; ++i) {
            float a   = sadj[i*NF + j];
            float msk = (a != 0.f) ? 1.f : 0.f;
            float v   = (a - mu) * rs * ln_gamma[i] + ln_beta[i];
            v += (1.f - msk) * (-1e9f);
            if (i == j) v += 1.f;
            xm[i] = v;
            mx = fmaxf(mx, v);
        }
        float se = 0.f;
        for (int i = 0; i < NF; ++i) { xm[i] = expf(xm[i] - mx); se += xm[i]; }
        float inv = 1.f / se;
        float av[NF];
        for (int i = 0; i < NF; ++i) {
            float a   = sadj[i*NF + j];
            float msk = (a != 0.f) ? 1.f : 0.f;
            av[i] = xm[i] * inv * msk;
        }
        #pragma unroll
        for (int p = 0; p < 20; ++p) {
            uint32_t hi, lo;
            splitpk(av[2*p], av[2*p+1], hi, lo);
            g_APH[t*1152 + j*24 + p] = hi;
            g_APL[t*1152 + j*24 + p] = lo;
        }
        #pragma unroll
        for (int p = 20; p < 24; ++p) {
            g_APH[t*1152 + j*24 + p] = 0u;
            g_APL[t*1152 + j*24 + p] = 0u;
        }
    } else if (tid >= 64 && tid < 72) {
        int n = 40 + (tid - 64);
        #pragma unroll
        for (int p = 0; p < 24; ++p) {
            g_APH[t*1152 + n*24 + p] = 0u;
            g_APL[t*1152 + n*24 + p] = 0u;
        }
    }
}

// ---------------- prep 2: sbp + wp + gp fused ----------------------------
__global__ void prep_misc(const float* __restrict__ bn_gamma,
                          const float* __restrict__ bn_beta,
                          const float* __restrict__ bn_mean,
                          const float* __restrict__ bn_var,
                          const float* __restrict__ gnn_w,
                          const float* __restrict__ gnn_b,
                          const float* __restrict__ gate_w) {
    int bid = blockIdx.x;
    int tid = threadIdx.x;
    if (bid < 80) {
        int t = bid / NF, n = bid - t*NF;
        __shared__ float so[128];
        if (tid < 128) {
            int F = bid*128 + tid;
            float s = bn_gamma[F] * rsqrtf(bn_var[F] + FEPS);
            float o = bn_beta[F] - bn_mean[F] * s;
            g_S[bid*128 + tid] = s;
            so[tid] = o;
        }
        __syncthreads();
        if (tid < DD) {
            float acc = gnn_b[t*NF*DD + n*DD + tid];
            #pragma unroll 8
            for (int f = 0; f < 128; ++f)
                acc += so[f] * gnn_w[t*128*DD + f*DD + tid];
            g_BP[bid*DD + tid] = acc;
        }
    } else if (bid < 112) {
        int i = (bid - 80)*256 + tid;
        if (i < TT*64*64) {
            int t = i >> 12, r = i & 4095;
            int p = r >> 6, d = r & 63;
            float w0 = gnn_w[t*8192 + (2*p)*64 + d];
            float w1 = gnn_w[t*8192 + (2*p+1)*64 + d];
            uint32_t hi, lo;
            splitpk(w0, w1, hi, lo);
            g_WPH[i] = hi;
            g_WPL[i] = lo;
        }
    } else {
        int i = (bid - 112)*256 + tid;
        if (i < NF*1280) {
            int c = i / 1280, p = i - c*1280;
            float w0 = gate_w[(2*p)*NF + c];
            float w1 = gate_w[(2*p+1)*NF + c];
            uint32_t hi, lo;
            splitpk(w0, w1, hi, lo);
            g_GPH[i] = hi;
            g_GPL[i] = lo;
        }
    }
}

// ---------------- kernel 1: split-bf16 MMA forward (CHUNK=2, R14) --------
#define SMF_XPH 0
#define SMF_XPL 3264
#define SMF_ATH 6528
#define SMF_ATL 7872
#define SMF_CPH 9216
#define SMF_CPL 14656
#define SMF_WPH 20096
#define SMF_WPL 24448
#define SMF_WORDS 28800
#define SM_FWD_BYTES (SMF_WORDS*4)
__global__ __launch_bounds__(256, 2)
void k_forward(const float* __restrict__ x) {
    extern __shared__ uint32_t sw[];
    uint32_t* sXPH = sw + SMF_XPH;
    uint32_t* sXPL = sw + SMF_XPL;
    uint32_t* sATH = sw + SMF_ATH;
    uint32_t* sATL = sw + SMF_ATL;
    uint32_t* sCPH = sw + SMF_CPH;
    uint32_t* sCPL = sw + SMF_CPL;
    uint32_t* sWPH = sw + SMF_WPH;
    uint32_t* sWPL = sw + SMF_WPL;
    uint32_t sbase = smem_u32(sw);

    int tid  = threadIdx.x;
    int wid  = tid >> 5, lane = tid & 31;
    int g    = lane >> 2, tg = lane & 3;
    uint32_t lrow = lane & 15;
    uint32_t lcol = (lane >> 4) << 2;
    int b0   = blockIdx.x * CHUNK;
    const float* xb = x + (size_t)b0 * NF * DD;

    for (int idx = tid; idx < 2560; idx += 256) {
        int p   = idx >> 7;
        int col = idx & 127;
        int c = col >> 6, d = col & 63;
        float x0 = __ldg(xb + c*2560 + (2*p)*64 + d);
        float x1 = __ldg(xb + c*2560 + (2*p+1)*64 + d);
        uint32_t h, l;
        splitpk(x0, x1, h, l);
        sXPH[p*136 + col] = h;
        sXPL[p*136 + col] = l;
    }
    for (int idx = tid; idx < 544; idx += 256) {
        sXPH[20*136 + idx] = 0u;
        sXPL[20*136 + idx] = 0u;
    }

    for (int t = 0; t < TT; ++t) {
        for (int idx = tid; idx < 1152; idx += 256) {
            int n = idx / 24, p = idx - n*24;
            sATH[n*28 + p] = g_APH[t*1152 + idx];
            sATL[n*28 + p] = g_APL[t*1152 + idx];
        }
        for (int idx = tid; idx < 1024; idx += 256) {
            int p = idx >> 4, dq = (idx & 15) * 4;
            *(uint4*)(sWPH + p*68 + dq) = *(const uint4*)(g_WPH + t*4096 + p*64 + dq);
            *(uint4*)(sWPL + p*68 + dq) = *(const uint4*)(g_WPL + t*4096 + p*64 + dq);
        }
        for (int idx = tid; idx < 1280; idx += 256) {
            int row = idx >> 4, q = idx & 15;
            int c = row / 40, n = row - c*40;
            float4 xv = __ldg((const float4*)(xb + c*2560 + n*64 + q*4));
            float4 sv = __ldg((const float4*)(g_S + t*NF*128 + n*128 + q*4));
            uint32_t h0, l0, h1, l1;
            splitpk(xv.x*sv.x, xv.y*sv.y, h0, l0);
            splitpk(xv.z*sv.z, xv.w*sv.w, h1, l1);
            *(uint2*)(sCPH + row*68 + q*2) = make_uint2(h0, h1);
            *(uint2*)(sCPL + row*68 + q*2) = make_uint2(l0, l1);
        }
        __syncthreads();

        // ---- phase A MMA ----
        {
            float ahh[3][2][4], axx[3][2][4];
            #pragma unroll
            for (int m = 0; m < 3; ++m)
                #pragma unroll
                for (int c2 = 0; c2 < 2; ++c2)
                    #pragma unroll
                    for (int j = 0; j < 4; ++j) { ahh[m][c2][j] = 0.f; axx[m][c2][j] = 0.f; }

            #pragma unroll
            for (int ks = 0; ks < 3; ++ks) {
                uint32_t bh0[2], bh1[2], bl0[2], bl1[2];
                #pragma unroll
                for (int c2 = 0; c2 < 2; ++c2) {
                    int colb = (wid*2 + c2)*8 + g;
                    bh0[c2] = sXPH[(ks*8 + tg)*136 + colb];
                    bh1[c2] = sXPH[(ks*8 + tg + 4)*136 + colb];
                    bl0[c2] = sXPL[(ks*8 + tg)*136 + colb];
                    bl1[c2] = sXPL[(ks*8 + tg + 4)*136 + colb];
                }
                #pragma unroll
                for (int mt = 0; mt < 3; ++mt) {
                    uint32_t ah = sbase + (SMF_ATH + (mt*16 + lrow)*28 + ks*8 + lcol)*4u;
                    uint32_t a0h, a1h, a2h, a3h, a0l, a1l, a2l, a3l;
                    ldsm4(a0h, a1h, a2h, a3h, ah);
                    ldsm4(a0l, a1l, a2l, a3l, ah + (SMF_ATL - SMF_ATH)*4u);
                    #pragma unroll
                    for (int c2 = 0; c2 < 2; ++c2) {
                        mma_bf16(ahh[mt][c2], a0h, a1h, a2h, a3h, bh0[c2], bh1[c2]);
                        mma_bf16(axx[mt][c2], a0h, a1h, a2h, a3h, bl0[c2], bl1[c2]);
                        mma_bf16(axx[mt][c2], a0l, a1l, a2l, a3l, bh0[c2], bh1[c2]);
                    }
                }
            }

            float2 svv[3][2][2];
            #pragma unroll
            for (int mt = 0; mt < 3; ++mt)
                #pragma unroll
                for (int c2 = 0; c2 < 2; ++c2) {
                    int col = (wid*2 + c2)*8 + tg*2;
                    int d = col & 63;
                    int r0 = mt*16 + g;
                    int r1 = r0 + 8;
                    svv[mt][c2][0] = (r0 < NF)
                        ? *(const float2*)(g_S + t*NF*128 + r0*128 + 64 + d)
                        : make_float2(0.f, 0.f);
                    svv[mt][c2][1] = (r1 < NF)
                        ? *(const float2*)(g_S + t*NF*128 + r1*128 + 64 + d)
                        : make_float2(0.f, 0.f);
                }
            #pragma unroll
            for (int mt = 0; mt < 3; ++mt) {
                #pragma unroll
                for (int c2 = 0; c2 < 2; ++c2) {
                    int col = (wid*2 + c2)*8 + tg*2;
                    int c = col >> 6, d = col & 63;
                    int r0 = mt*16 + g;
                    if (r0 < NF) {
                        float2 sv = svv[mt][c2][0];
                        uint32_t h, l;
                        splitpk((ahh[mt][c2][0]+axx[mt][c2][0])*sv.x,
                                (ahh[mt][c2][1]+axx[mt][c2][1])*sv.y, h, l);
                        sCPH[(c*40 + r0)*68 + 32 + (d>>1)] = h;
                        sCPL[(c*40 + r0)*68 + 32 + (d>>1)] = l;
                    }
                    int r1 = mt*16 + 8 + g;
                    if (r1 < NF) {
                        float2 sv = svv[mt][c2][1];
                        uint32_t h, l;
                        splitpk((ahh[mt][c2][2]+axx[mt][c2][2])*sv.x,
                                (ahh[mt][c2][3]+axx[mt][c2][3])*sv.y, h, l);
                        sCPH[(c*40 + r1)*68 + 32 + (d>>1)] = h;
                        sCPL[(c*40 + r1)*68 + 32 + (d>>1)] = l;
                    }
                }
            }
        }
        __syncthreads();

        // ---- phase B MMA ----
        {
            float hhacc[5][4], xxacc[5][4];
            #pragma unroll
            for (int m = 0; m < 5; ++m)
                #pragma unroll
                for (int j = 0; j < 4; ++j) { hhacc[m][j] = 0.f; xxacc[m][j] = 0.f; }

            #pragma unroll
            for (int s = 0; s < 8; ++s) {
                int pb0 = (8*s + tg)*68     + wid*8 + g;
                int pb1 = (8*s + tg + 4)*68 + wid*8 + g;
                uint32_t b0h = sWPH[pb0], b1h = sWPH[pb1];
                uint32_t b0l = sWPL[pb0], b1l = sWPL[pb1];
                #pragma unroll
                for (int m = 0; m < 5; ++m) {
                    uint32_t ah = sbase + (SMF_CPH + (m*16 + lrow)*68 + 8*s + lcol)*4u;
                    uint32_t a0h, a1h, a2h, a3h, a0l, a1l, a2l, a3l;
                    ldsm4(a0h, a1h, a2h, a3h, ah);
                    ldsm4(a0l, a1l, a2l, a3l, ah + (SMF_CPL - SMF_CPH)*4u);
                    mma_bf16(hhacc[m], a0h, a1h, a2h, a3h, b0h, b1h);
                    mma_bf16(xxacc[m], a0h, a1h, a2h, a3h, b0l, b1l);
                    mma_bf16(xxacc[m], a0l, a1l, a2l, a3l, b0h, b1h);
                }
            }

            int d = wid*8 + tg*2;
            int pq = wid*4 + tg;
            float2 bpv[5][2];
            #pragma unroll
            for (int m = 0; m < 5; ++m) {
                int r0 = m*16 + g, r1 = r0 + 8;
                int n0 = r0 - (r0/40)*40, n1 = r1 - (r1/40)*40;
                bpv[m][0] = *(const float2*)(g_BP + t*2560 + n0*64 + d);
                bpv[m][1] = *(const float2*)(g_BP + t*2560 + n1*64 + d);
            }
            uint32_t hh[5][2], ll[5][2];
            #pragma unroll
            for (int m = 0; m < 5; ++m) {
                splitpk(hhacc[m][0] + xxacc[m][0] + bpv[m][0].x,
                        hhacc[m][1] + xxacc[m][1] + bpv[m][0].y, hh[m][0], ll[m][0]);
                splitpk(hhacc[m][2] + xxacc[m][2] + bpv[m][1].x,
                        hhacc[m][3] + xxacc[m][3] + bpv[m][1].y, hh[m][1], ll[m][1]);
            }
            __syncthreads();
            #pragma unroll
            for (int m = 0; m < 5; ++m) {
                int r0 = m*16 + g, r1 = r0 + 8;
                sCPH[r0*36 + pq] = hh[m][0];  sCPL[r0*36 + pq] = ll[m][0];
                sCPH[r1*36 + pq] = hh[m][1];  sCPL[r1*36 + pq] = ll[m][1];
            }
            __syncthreads();
            for (int idx = tid; idx < 640; idx += 256) {
                int r = idx >> 3, j = idx & 7;
                int c = r / 40, n = r - c*40;
                size_t dst = (size_t)((b0 + c)*TT + t) * 1280 + n*32 + j*4;
                *(uint4*)(g_HH + dst) = *(const uint4*)(sCPH + r*36 + j*4);
                *(uint4*)(g_HL + dst) = *(const uint4*)(sCPL + r*36 + j*4);
            }
        }
        __syncthreads();
    }
}

// ---------------- kernel 2: gate, M-tile 32, 4-way ks-split ---------------
// 256 threads = 8 warps: warp = (kg 0..3, mw 0..1). 3-buffer cp.async ring.
#define ASTR 36
#define AH_W (32*ASTR)            // 1152 words
#define BH_W (NF*ASTR)            // 1440 words
#define BUF_W (2*AH_W + 2*BH_W)   // 5184 words
#define GSM_WORDS (3*BUF_W)       // 15552 words = 62208 B
__device__ __forceinline__ void gate_issue_chunk_nc(uint32_t bufb, int row0, int ck, int tid) {
    {   // A tiles: 32 rows x 8 uint4, exactly 256 threads
        int r = tid >> 3, j = tid & 7;
        uint32_t dst = bufb + (uint32_t)(r*ASTR + j*4)*4u;
        cpa16(dst, g_HH + (size_t)(row0 + r)*1280 + ck*32 + j*4);
        cpa16(dst + AH_W*4u, g_HL + (size_t)(row0 + r)*1280 + ck*32 + j*4);
    }
    #pragma unroll
    for (int q = 0; q < 2; ++q) {
        int idx = tid + q*256;
        if (idx < 320) {
            int c = idx >> 3, j = idx & 7;
            uint32_t dst = bufb + (uint32_t)(2*AH_W + c*ASTR + j*4)*4u;
            cpa16(dst, g_GPH + c*1280 + ck*32 + j*4);
            cpa16(dst + BH_W*4u, g_GPL + c*1280 + ck*32 + j*4);
        }
    }
}
__global__ __launch_bounds__(256, 3)
void k_gate(const float* __restrict__ gate_b, float* __restrict__ out) {
    extern __shared__ uint32_t gw[];
    uint32_t gb = smem_u32(gw);
    int tid  = threadIdx.x;
    int wid  = tid >> 5, lane = tid & 31;
    int kg   = wid >> 1;        // ks-group 0..3 (one 8-pair K slice each)
    int mw   = wid & 1;         // m-tile 0..1
    int g    = lane >> 2, tg = lane & 3;
    uint32_t lrow = lane & 15;
    uint32_t lcol = (lane >> 4) << 2;
    int row0 = blockIdx.x * 32;

    float hhacc[5][4], xxacc[5][4];
    #pragma unroll
    for (int m = 0; m < 5; ++m)
        #pragma unroll
        for (int j = 0; j < 4; ++j) { hhacc[m][j] = 0.f; xxacc[m][j] = 0.f; }

    gate_issue_chunk_nc(gb, row0, 0, tid);
    CPA_COMMIT();
    gate_issue_chunk_nc(gb + (uint32_t)BUF_W*4u, row0, 1, tid);
    CPA_COMMIT();

    for (int ck = 0; ck < 40; ++ck) {
        if (ck + 1 < 40) { CPA_WAIT(1); } else { CPA_WAIT(0); }
        __syncthreads();

        int buf = ck % 3;
        const uint32_t* Bh = gw + buf*BUF_W + 2*AH_W;
        const uint32_t* Bl = Bh + BH_W;
        uint32_t abase = gb + (uint32_t)(buf*BUF_W)*4u;

        int ko = kg*8;
        uint32_t ah = abase + ((mw*16 + lrow)*ASTR + ko + lcol)*4u;
        uint32_t a0h, a1h, a2h, a3h, a0l, a1l, a2l, a3l;
        ldsm4(a0h, a1h, a2h, a3h, ah);
        ldsm4(a0l, a1l, a2l, a3l, ah + AH_W*4u);
        #pragma unroll
        for (int nt = 0; nt < 5; ++nt) {
            int pb = (nt*8 + g)*ASTR + ko + tg;
            uint32_t b0h = Bh[pb], b1h = Bh[pb+4];
            uint32_t b0l = Bl[pb], b1l = Bl[pb+4];
            mma_bf16(hhacc[nt], a0h, a1h, a2h, a3h, b0h, b1h);
            mma_bf16(xxacc[nt], a0h, a1h, a2h, a3h, b0l, b1l);
            mma_bf16(xxacc[nt], a0l, a1l, a2l, a3l, b0h, b1h);
        }
        __syncthreads();
        if (ck + 2 < 40) {
            gate_issue_chunk_nc(gb + (uint32_t)(((ck + 2) % 3) * BUF_W)*4u, row0, ck + 2, tid);
            CPA_COMMIT();
        }
    }

    float acc[5][4];
    #pragma unroll
    for (int m = 0; m < 5; ++m)
        #pragma unroll
        for (int j = 0; j < 4; ++j) acc[m][j] = hhacc[m][j] + xxacc[m][j];

    // ---- reduce kg1..3 into kg0 via smem ----
    float* sRed = (float*)gw;
    int sub = mw*32 + lane;     // 0..63 within ks-group
    if (kg > 0) {
        int base = ((kg - 1)*64 + sub) * 20;
        #pragma unroll
        for (int m = 0; m < 5; ++m)
            #pragma unroll
            for (int j = 0; j < 4; ++j) sRed[base + m*4 + j] = acc[m][j];
    }
    __syncthreads();
    if (kg == 0) {
        #pragma unroll
        for (int s = 0; s < 3; ++s) {
            int base = (s*64 + sub) * 20;
            #pragma unroll
            for (int m = 0; m < 5; ++m)
                #pragma unroll
                for (int j = 0; j < 4; ++j) acc[m][j] += sRed[base + m*4 + j];
        }
    }
    __syncthreads();

    float* sL = (float*)(gw + 4096);   // [32][41]
    if (kg == 0) {
        #pragma unroll
        for (int nt = 0; nt < 5; ++nt) {
            int col = nt*8 + tg*2;
            float b0 = __ldg(gate_b + col);
            float b1 = __ldg(gate_b + col + 1);
            sL[(mw*16 + g)*41 + col]         = acc[nt][0] + b0;
            sL[(mw*16 + g)*41 + col + 1]     = acc[nt][1] + b1;
            sL[(mw*16 + 8 + g)*41 + col]     = acc[nt][2] + b0;
            sL[(mw*16 + 8 + g)*41 + col + 1] = acc[nt][3] + b1;
        }
    }
    __syncthreads();

    if (tid < 32) {
        float* lp = sL + tid*41;
        float mx = -1e30f;
        #pragma unroll 8
        for (int n = 0; n < NF; ++n) mx = fmaxf(mx, lp[n]);
        float se = 0.f;
        #pragma unroll 8
        for (int n = 0; n < NF; ++n) se += expf(lp[n] - mx);
        float inv = 1.f / se;
        #pragma unroll 8
        for (int n = 0; n < NF; ++n) lp[n] = expf(lp[n] - mx) * inv;
    }
    __syncthreads();

    // pool: 8 threads per row, 4 pairs each
    {
        int row = tid >> 3;
        int q   = tid & 7;
        int pb  = q * 4;
        const uint32_t* hh = g_HH + (size_t)(row0 + row)*1280 + pb;
        const uint32_t* hl = g_HL + (size_t)(row0 + row)*1280 + pb;
        const float* wp = sL + row*41;
        float2 a2[4];
        #pragma unroll
        for (int k = 0; k < 4; ++k) a2[k] = make_float2(0.f, 0.f);
        #pragma unroll 4
        for (int n = 0; n < NF; ++n) {
            float wv = wp[n];
            uint4 hv = *(const uint4*)(hh + n*32);
            uint4 lv = *(const uint4*)(hl + n*32);
            float2 f0 = rec2(hv.x, lv.x), f1 = rec2(hv.y, lv.y);
            float2 f2 = rec2(hv.z, lv.z), f3 = rec2(hv.w, lv.w);
            a2[0].x += wv*f0.x; a2[0].y += wv*f0.y;
            a2[1].x += wv*f1.x; a2[1].y += wv*f1.y;
            a2[2].x += wv*f2.x; a2[2].y += wv*f2.y;
            a2[3].x += wv*f3.x; a2[3].y += wv*f3.y;
        }
        float* op = out + (size_t)(row0 + row)*64 + q*8;
        *(float4*)(op)     = make_float4(a2[0].x, a2[0].y, a2[1].x, a2[1].y);
        *(float4*)(op + 4) = make_float4(a2[2].x, a2[2].y, a2[3].x, a2[3].y);
    }
}

// ---------------- launcher ------------------------------------------------
extern "C" void kernel_launch(void* const* d_in, const int* in_sizes, int n_in,
                              void* d_out, int out_size) {
    const float* x        = (const float*)d_in[0];
    const float* masker   = (const float*)d_in[1];
    const float* ln_gamma = (const float*)d_in[2];
    const float* ln_beta  = (const float*)d_in[3];
    const float* gnn_w    = (const float*)d_in[4];
    const float* gnn_b    = (const float*)d_in[5];
    const float* bn_gamma = (const float*)d_in[6];
    const float* bn_beta  = (const float*)d_in[7];
    const float* bn_mean  = (const float*)d_in[8];
    const float* bn_var   = (const float*)d_in[9];
    const float* gate_w   = (const float*)d_in[10];
    const float* gate_b   = (const float*)d_in[11];
    float* out = (float*)d_out;

    cudaFuncSetAttribute(k_forward, cudaFuncAttributeMaxDynamicSharedMemorySize,
                         SM_FWD_BYTES);
    cudaFuncSetAttribute(k_gate, cudaFuncAttributeMaxDynamicSharedMemorySize,
                         GSM_WORDS * (int)sizeof(uint32_t));

    prep_adj<<<2, 128>>>(masker, ln_gamma, ln_beta);
    prep_misc<<<312, 256>>>(bn_gamma, bn_beta, bn_mean, bn_var, gnn_w, gnn_b, gate_w);
    k_forward<<<BSZ / CHUNK, 256, SM_FWD_BYTES>>>(x);
    k_gate<<<BSZ * TT / 32, 256, GSM_WORDS * sizeof(uint32_t)>>>(gate_b, out);
}

// round 17
// speedup vs baseline: 1.3792x; 1.1735x over previous
#include <cuda_runtime.h>
#include <cuda_bf16.h>
#include <math.h>
#include <stdint.h>

#define BSZ   8192
#define TT    2
#define NF    40
#define DD    64
#define FEPS  1e-5f
#define CHUNK 2

typedef unsigned long long u64;

// ---- split-bf16: (a,b) -> hi pair + residual pair ----
__device__ __forceinline__ void splitpk(float a, float b, uint32_t& hi, uint32_t& lo) {
    __nv_bfloat162 h = __floats2bfloat162_rn(a, b);
    float ra = a - __bfloat162float(h.x);
    float rb = b - __bfloat162float(h.y);
    __nv_bfloat162 l = __floats2bfloat162_rn(ra, rb);
    hi = *reinterpret_cast<uint32_t*>(&h);
    lo = *reinterpret_cast<uint32_t*>(&l);
}
__device__ __forceinline__ float2 rec2(uint32_t h, uint32_t l) {
    float2 hf = __bfloat1622float2(*reinterpret_cast<__nv_bfloat162*>(&h));
    float2 lf = __bfloat1622float2(*reinterpret_cast<__nv_bfloat162*>(&l));
    return make_float2(hf.x + lf.x, hf.y + lf.y);
}

// ---- legacy tensor core mma (sm_80+) ----
__device__ __forceinline__ void mma_bf16(float* d,
    uint32_t a0, uint32_t a1, uint32_t a2, uint32_t a3,
    uint32_t b0, uint32_t b1) {
    asm volatile(
        "mma.sync.aligned.m16n8k16.row.col.f32.bf16.bf16.f32 "
        "{%0,%1,%2,%3}, {%4,%5,%6,%7}, {%8,%9}, {%0,%1,%2,%3};"
        : "+f"(d[0]), "+f"(d[1]), "+f"(d[2]), "+f"(d[3])
        : "r"(a0), "r"(a1), "r"(a2), "r"(a3), "r"(b0), "r"(b1));
}

// ---- ldmatrix x4 (sm_75+) ----
__device__ __forceinline__ void ldsm4(uint32_t& r0, uint32_t& r1,
                                      uint32_t& r2, uint32_t& r3, uint32_t addr) {
    asm volatile("ldmatrix.sync.aligned.m8n8.x4.shared.b16 {%0,%1,%2,%3}, [%4];"
        : "=r"(r0), "=r"(r1), "=r"(r2), "=r"(r3) : "r"(addr));
}

// ---- cp.async (sm_80+) ----
__device__ __forceinline__ uint32_t smem_u32(const void* p) {
    uint32_t a;
    asm("{ .reg .u64 t; cvta.to.shared.u64 t, %1; cvt.u32.u64 %0, t; }" : "=r"(a) : "l"(p));
    return a;
}
__device__ __forceinline__ void cpa16(uint32_t dst, const void* src) {
    asm volatile("cp.async.cg.shared.global [%0], [%1], 16;" :: "r"(dst), "l"(src));
}
#define CPA_COMMIT() asm volatile("cp.async.commit_group;" ::: "memory")
#define CPA_WAIT(n)  asm volatile("cp.async.wait_group %0;" :: "n"(n) : "memory")

// ---------------- device scratch ----------------
__device__ float g_S [TT*NF*128];
__device__ float g_BP[TT*NF*DD];
__device__ uint32_t g_WPH[TT*64*64];
__device__ uint32_t g_WPL[TT*64*64];
__device__ uint32_t g_APH[TT*48*24];
__device__ uint32_t g_APL[TT*48*24];
__device__ uint32_t g_HH[(size_t)BSZ*TT*1280];
__device__ uint32_t g_HL[(size_t)BSZ*TT*1280];
__device__ uint32_t g_GPH[NF*1280];
__device__ uint32_t g_GPL[NF*1280];

// ---------------- prep 1: adj -> LN -> mask -> softmax -> A^T split pairs --
__global__ void prep_adj(const float* __restrict__ masker,
                         const float* __restrict__ ln_gamma,
                         const float* __restrict__ ln_beta) {
    int t = blockIdx.x;
    __shared__ float sadj[NF*NF];
    int tid = threadIdx.x;
    const float* mk = masker + (size_t)t * 3 * NF * NF;
    for (int i = tid; i < NF*NF; i += blockDim.x) {
        float p = mk[i] * mk[NF*NF + i] * mk[2*NF*NF + i];
        sadj[i] = p > 0.f ? p : 0.f;
    }
    __syncthreads();
    if (tid < NF) {
        int j = tid;
        float sum = 0.f, sq = 0.f;
        for (int i = 0; i < NF; ++i) { float a = sadj[i*NF + j]; sum += a; sq += a*a; }
        float mu  = sum * (1.f/NF);
        float var = sq * (1.f/NF) - mu*mu;
        float rs  = rsqrtf(var + FEPS);
        float xm[NF];
        float mx = -1e30f;
        for (int i = 0; i < NF; ++i) {
            float a   = sadj[i*NF + j];
            float msk = (a != 0.f) ? 1.f : 0.f;
            float v   = (a - mu) * rs * ln_gamma[i] + ln_beta[i];
            v += (1.f - msk) * (-1e9f);
            if (i == j) v += 1.f;
            xm[i] = v;
            mx = fmaxf(mx, v);
        }
        float se = 0.f;
        for (int i = 0; i < NF; ++i) { xm[i] = expf(xm[i] - mx); se += xm[i]; }
        float inv = 1.f / se;
        float av[NF];
        for (int i = 0; i < NF; ++i) {
            float a   = sadj[i*NF + j];
            float msk = (a != 0.f) ? 1.f : 0.f;
            av[i] = xm[i] * inv * msk;
        }
        #pragma unroll
        for (int p = 0; p < 20; ++p) {
            uint32_t hi, lo;
            splitpk(av[2*p], av[2*p+1], hi, lo);
            g_APH[t*1152 + j*24 + p] = hi;
            g_APL[t*1152 + j*24 + p] = lo;
        }
        #pragma unroll
        for (int p = 20; p < 24; ++p) {
            g_APH[t*1152 + j*24 + p] = 0u;
            g_APL[t*1152 + j*24 + p] = 0u;
        }
    } else if (tid >= 64 && tid < 72) {
        int n = 40 + (tid - 64);
        #pragma unroll
        for (int p = 0; p < 24; ++p) {
            g_APH[t*1152 + n*24 + p] = 0u;
            g_APL[t*1152 + n*24 + p] = 0u;
        }
    }
}

// ---------------- prep 2: sbp + wp + gp fused ----------------------------
__global__ void prep_misc(const float* __restrict__ bn_gamma,
                          const float* __restrict__ bn_beta,
                          const float* __restrict__ bn_mean,
                          const float* __restrict__ bn_var,
                          const float* __restrict__ gnn_w,
                          const float* __restrict__ gnn_b,
                          const float* __restrict__ gate_w) {
    int bid = blockIdx.x;
    int tid = threadIdx.x;
    if (bid < 80) {
        int t = bid / NF, n = bid - t*NF;
        __shared__ float so[128];
        if (tid < 128) {
            int F = bid*128 + tid;
            float s = bn_gamma[F] * rsqrtf(bn_var[F] + FEPS);
            float o = bn_beta[F] - bn_mean[F] * s;
            g_S[bid*128 + tid] = s;
            so[tid] = o;
        }
        __syncthreads();
        if (tid < DD) {
            float acc = gnn_b[t*NF*DD + n*DD + tid];
            #pragma unroll 8
            for (int f = 0; f < 128; ++f)
                acc += so[f] * gnn_w[t*128*DD + f*DD + tid];
            g_BP[bid*DD + tid] = acc;
        }
    } else if (bid < 112) {
        int i = (bid - 80)*256 + tid;
        if (i < TT*64*64) {
            int t = i >> 12, r = i & 4095;
            int p = r >> 6, d = r & 63;
            float w0 = gnn_w[t*8192 + (2*p)*64 + d];
            float w1 = gnn_w[t*8192 + (2*p+1)*64 + d];
            uint32_t hi, lo;
            splitpk(w0, w1, hi, lo);
            g_WPH[i] = hi;
            g_WPL[i] = lo;
        }
    } else {
        int i = (bid - 112)*256 + tid;
        if (i < NF*1280) {
            int c = i / 1280, p = i - c*1280;
            float w0 = gate_w[(2*p)*NF + c];
            float w1 = gate_w[(2*p+1)*NF + c];
            uint32_t hi, lo;
            splitpk(w0, w1, hi, lo);
            g_GPH[i] = hi;
            g_GPL[i] = lo;
        }
    }
}

// ---------------- forward staging helpers (cp.async) ----------------------
__device__ __forceinline__ void issue_at(uint32_t sb_ath, uint32_t sb_atl, int t, int tid) {
    for (int idx = tid; idx < 288; idx += 256) {     // 48 rows x 6 x 16B
        int n = idx / 6, j = idx - n*6;
        uint32_t off = (uint32_t)(n*28 + j*4)*4u;
        cpa16(sb_ath + off, g_APH + t*1152 + n*24 + j*4);
        cpa16(sb_atl + off, g_APL + t*1152 + n*24 + j*4);
    }
}
__device__ __forceinline__ void issue_w(uint32_t sb_wph, uint32_t sb_wpl, int t, int tid) {
    #pragma unroll
    for (int q = 0; q < 4; ++q) {                    // 64 rows x 16 x 16B
        int idx = tid + q*256;
        int p = idx >> 4, j = idx & 15;
        uint32_t off = (uint32_t)(p*68 + j*4)*4u;
        cpa16(sb_wph + off, g_WPH + t*4096 + p*64 + j*4);
        cpa16(sb_wpl + off, g_WPL + t*4096 + p*64 + j*4);
    }
}

// ---------------- kernel 1: split-bf16 MMA forward (CHUNK=2) --------------
#define SMF_XPH 0
#define SMF_XPL 3264
#define SMF_ATH 6528
#define SMF_ATL 7872
#define SMF_CPH 9216
#define SMF_CPL 14656
#define SMF_WPH 20096
#define SMF_WPL 24448
#define SMF_WORDS 28800
#define SM_FWD_BYTES (SMF_WORDS*4)
__global__ __launch_bounds__(256, 2)
void k_forward(const float* __restrict__ x) {
    extern __shared__ uint32_t sw[];
    uint32_t* sXPH = sw + SMF_XPH;
    uint32_t* sXPL = sw + SMF_XPL;
    uint32_t* sCPH = sw + SMF_CPH;
    uint32_t* sCPL = sw + SMF_CPL;
    uint32_t* sWPH = sw + SMF_WPH;
    uint32_t* sWPL = sw + SMF_WPL;
    uint32_t sbase = smem_u32(sw);

    int tid  = threadIdx.x;
    int wid  = tid >> 5, lane = tid & 31;
    int g    = lane >> 2, tg = lane & 3;
    uint32_t lrow = lane & 15;
    uint32_t lcol = (lane >> 4) << 2;
    int b0   = blockIdx.x * CHUNK;
    const float* xb = x + (size_t)b0 * NF * DD;

    // prefetch AT(t0) + W(t0) while we build XP
    issue_at(sbase + SMF_ATH*4u, sbase + SMF_ATL*4u, 0, tid);
    issue_w (sbase + SMF_WPH*4u, sbase + SMF_WPL*4u, 0, tid);
    CPA_COMMIT();

    for (int idx = tid; idx < 2560; idx += 256) {
        int p   = idx >> 7;
        int col = idx & 127;
        int c = col >> 6, d = col & 63;
        float x0 = __ldg(xb + c*2560 + (2*p)*64 + d);
        float x1 = __ldg(xb + c*2560 + (2*p+1)*64 + d);
        uint32_t h, l;
        splitpk(x0, x1, h, l);
        sXPH[p*136 + col] = h;
        sXPL[p*136 + col] = l;
    }
    for (int idx = tid; idx < 544; idx += 256) {
        sXPH[20*136 + idx] = 0u;
        sXPL[20*136 + idx] = 0u;
    }

    for (int t = 0; t < TT; ++t) {
        // cat lower half: x * s_lo -> pairs (AT/W arrive via cp.async)
        for (int idx = tid; idx < 1280; idx += 256) {
            int row = idx >> 4, q = idx & 15;
            int c = row / 40, n = row - c*40;
            float4 xv = __ldg((const float4*)(xb + c*2560 + n*64 + q*4));
            float4 sv = __ldg((const float4*)(g_S + t*NF*128 + n*128 + q*4));
            uint32_t h0, l0, h1, l1;
            splitpk(xv.x*sv.x, xv.y*sv.y, h0, l0);
            splitpk(xv.z*sv.z, xv.w*sv.w, h1, l1);
            *(uint2*)(sCPH + row*68 + q*2) = make_uint2(h0, h1);
            *(uint2*)(sCPL + row*68 + q*2) = make_uint2(l0, l1);
        }
        CPA_WAIT(0);
        __syncthreads();

        // ---- phase A MMA ----
        {
            float ahh[3][2][4], axx[3][2][4];
            #pragma unroll
            for (int m = 0; m < 3; ++m)
                #pragma unroll
                for (int c2 = 0; c2 < 2; ++c2)
                    #pragma unroll
                    for (int j = 0; j < 4; ++j) { ahh[m][c2][j] = 0.f; axx[m][c2][j] = 0.f; }

            #pragma unroll
            for (int ks = 0; ks < 3; ++ks) {
                uint32_t bh0[2], bh1[2], bl0[2], bl1[2];
                #pragma unroll
                for (int c2 = 0; c2 < 2; ++c2) {
                    int colb = (wid*2 + c2)*8 + g;
                    bh0[c2] = sXPH[(ks*8 + tg)*136 + colb];
                    bh1[c2] = sXPH[(ks*8 + tg + 4)*136 + colb];
                    bl0[c2] = sXPL[(ks*8 + tg)*136 + colb];
                    bl1[c2] = sXPL[(ks*8 + tg + 4)*136 + colb];
                }
                #pragma unroll
                for (int mt = 0; mt < 3; ++mt) {
                    uint32_t ah = sbase + (SMF_ATH + (mt*16 + lrow)*28 + ks*8 + lcol)*4u;
                    uint32_t a0h, a1h, a2h, a3h, a0l, a1l, a2l, a3l;
                    ldsm4(a0h, a1h, a2h, a3h, ah);
                    ldsm4(a0l, a1l, a2l, a3l, ah + (SMF_ATL - SMF_ATH)*4u);
                    #pragma unroll
                    for (int c2 = 0; c2 < 2; ++c2) {
                        mma_bf16(ahh[mt][c2], a0h, a1h, a2h, a3h, bh0[c2], bh1[c2]);
                        mma_bf16(axx[mt][c2], a0h, a1h, a2h, a3h, bl0[c2], bl1[c2]);
                        mma_bf16(axx[mt][c2], a0l, a1l, a2l, a3l, bh0[c2], bh1[c2]);
                    }
                }
            }

            float2 svv[3][2][2];
            #pragma unroll
            for (int mt = 0; mt < 3; ++mt)
                #pragma unroll
                for (int c2 = 0; c2 < 2; ++c2) {
                    int col = (wid*2 + c2)*8 + tg*2;
                    int d = col & 63;
                    int r0 = mt*16 + g;
                    int r1 = r0 + 8;
                    svv[mt][c2][0] = (r0 < NF)
                        ? *(const float2*)(g_S + t*NF*128 + r0*128 + 64 + d)
                        : make_float2(0.f, 0.f);
                    svv[mt][c2][1] = (r1 < NF)
                        ? *(const float2*)(g_S + t*NF*128 + r1*128 + 64 + d)
                        : make_float2(0.f, 0.f);
                }
            #pragma unroll
            for (int mt = 0; mt < 3; ++mt) {
                #pragma unroll
                for (int c2 = 0; c2 < 2; ++c2) {
                    int col = (wid*2 + c2)*8 + tg*2;
                    int c = col >> 6, d = col & 63;
                    int r0 = mt*16 + g;
                    if (r0 < NF) {
                        float2 sv = svv[mt][c2][0];
                        uint32_t h, l;
                        splitpk((ahh[mt][c2][0]+axx[mt][c2][0])*sv.x,
                                (ahh[mt][c2][1]+axx[mt][c2][1])*sv.y, h, l);
                        sCPH[(c*40 + r0)*68 + 32 + (d>>1)] = h;
                        sCPL[(c*40 + r0)*68 + 32 + (d>>1)] = l;
                    }
                    int r1 = mt*16 + 8 + g;
                    if (r1 < NF) {
                        float2 sv = svv[mt][c2][1];
                        uint32_t h, l;
                        splitpk((ahh[mt][c2][2]+axx[mt][c2][2])*sv.x,
                                (ahh[mt][c2][3]+axx[mt][c2][3])*sv.y, h, l);
                        sCPH[(c*40 + r1)*68 + 32 + (d>>1)] = h;
                        sCPL[(c*40 + r1)*68 + 32 + (d>>1)] = l;
                    }
                }
            }
        }
        __syncthreads();

        // AT no longer read this t: prefetch next tower's AT during phase B
        if (t == 0) {
            issue_at(sbase + SMF_ATH*4u, sbase + SMF_ATL*4u, 1, tid);
            CPA_COMMIT();
        }

        // ---- phase B MMA ----
        {
            float hhacc[5][4], xxacc[5][4];
            #pragma unroll
            for (int m = 0; m < 5; ++m)
                #pragma unroll
                for (int j = 0; j < 4; ++j) { hhacc[m][j] = 0.f; xxacc[m][j] = 0.f; }

            #pragma unroll
            for (int s = 0; s < 8; ++s) {
                int pb0 = (8*s + tg)*68     + wid*8 + g;
                int pb1 = (8*s + tg + 4)*68 + wid*8 + g;
                uint32_t b0h = sWPH[pb0], b1h = sWPH[pb1];
                uint32_t b0l = sWPL[pb0], b1l = sWPL[pb1];
                #pragma unroll
                for (int m = 0; m < 5; ++m) {
                    uint32_t ah = sbase + (SMF_CPH + (m*16 + lrow)*68 + 8*s + lcol)*4u;
                    uint32_t a0h, a1h, a2h, a3h, a0l, a1l, a2l, a3l;
                    ldsm4(a0h, a1h, a2h, a3h, ah);
                    ldsm4(a0l, a1l, a2l, a3l, ah + (SMF_CPL - SMF_CPH)*4u);
                    mma_bf16(hhacc[m], a0h, a1h, a2h, a3h, b0h, b1h);
                    mma_bf16(xxacc[m], a0h, a1h, a2h, a3h, b0l, b1l);
                    mma_bf16(xxacc[m], a0l, a1l, a2l, a3l, b0h, b1h);
                }
            }

            int d = wid*8 + tg*2;
            int pq = wid*4 + tg;
            float2 bpv[5][2];
            #pragma unroll
            for (int m = 0; m < 5; ++m) {
                int r0 = m*16 + g, r1 = r0 + 8;
                int n0 = r0 - (r0/40)*40, n1 = r1 - (r1/40)*40;
                bpv[m][0] = *(const float2*)(g_BP + t*2560 + n0*64 + d);
                bpv[m][1] = *(const float2*)(g_BP + t*2560 + n1*64 + d);
            }
            uint32_t hh[5][2], ll[5][2];
            #pragma unroll
            for (int m = 0; m < 5; ++m) {
                splitpk(hhacc[m][0] + xxacc[m][0] + bpv[m][0].x,
                        hhacc[m][1] + xxacc[m][1] + bpv[m][0].y, hh[m][0], ll[m][0]);
                splitpk(hhacc[m][2] + xxacc[m][2] + bpv[m][1].x,
                        hhacc[m][3] + xxacc[m][3] + bpv[m][1].y, hh[m][1], ll[m][1]);
            }
            __syncthreads();   // all warps done reading cat smem + W tiles

            // W no longer read this t: prefetch next tower's W during stores
            if (t == 0) {
                issue_w(sbase + SMF_WPH*4u, sbase + SMF_WPL*4u, 1, tid);
                CPA_COMMIT();
            }

            #pragma unroll
            for (int m = 0; m < 5; ++m) {
                int r0 = m*16 + g, r1 = r0 + 8;
                sCPH[r0*36 + pq] = hh[m][0];  sCPL[r0*36 + pq] = ll[m][0];
                sCPH[r1*36 + pq] = hh[m][1];  sCPL[r1*36 + pq] = ll[m][1];
            }
            __syncthreads();
            for (int idx = tid; idx < 640; idx += 256) {
                int r = idx >> 3, j = idx & 7;
                int c = r / 40, n = r - c*40;
                size_t dst = (size_t)((b0 + c)*TT + t) * 1280 + n*32 + j*4;
                *(uint4*)(g_HH + dst) = *(const uint4*)(sCPH + r*36 + j*4);
                *(uint4*)(g_HL + dst) = *(const uint4*)(sCPL + r*36 + j*4);
            }
        }
        __syncthreads();
    }
}

// ---------------- kernel 2: gate (exact R14), M=64, 2-way ks-split --------
#define ASTR 36
#define AH_W (64*ASTR)
#define BH_W (NF*ASTR)
#define BUF_W (2*AH_W + 2*BH_W)
#define GSM_WORDS (3*BUF_W)
__device__ __forceinline__ void gate_issue_chunk_nc(uint32_t bufb, int row0, int ck, int tid) {
    #pragma unroll
    for (int q = 0; q < 2; ++q) {
        int idx = tid + q*256;
        int r = idx >> 3, j = idx & 7;
        uint32_t dst = bufb + (uint32_t)(r*ASTR + j*4)*4u;
        cpa16(dst, g_HH + (size_t)(row0 + r)*1280 + ck*32 + j*4);
        cpa16(dst + AH_W*4u, g_HL + (size_t)(row0 + r)*1280 + ck*32 + j*4);
    }
    #pragma unroll
    for (int q = 0; q < 2; ++q) {
        int idx = tid + q*256;
        if (idx < 320) {
            int c = idx >> 3, j = idx & 7;
            uint32_t dst = bufb + (uint32_t)(2*AH_W + c*ASTR + j*4)*4u;
            cpa16(dst, g_GPH + c*1280 + ck*32 + j*4);
            cpa16(dst + BH_W*4u, g_GPL + c*1280 + ck*32 + j*4);
        }
    }
}
__global__ __launch_bounds__(256, 2)
void k_gate(const float* __restrict__ gate_b, float* __restrict__ out) {
    extern __shared__ uint32_t gw[];
    uint32_t gb = smem_u32(gw);
    int tid  = threadIdx.x;
    int wid  = tid >> 5, lane = tid & 31;
    int kg   = wid >> 2;
    int mw   = wid & 3;
    int g    = lane >> 2, tg = lane & 3;
    uint32_t lrow = lane & 15;
    uint32_t lcol = (lane >> 4) << 2;
    int row0 = blockIdx.x * 64;

    float hhacc[5][4], xxacc[5][4];
    #pragma unroll
    for (int m = 0; m < 5; ++m)
        #pragma unroll
        for (int j = 0; j < 4; ++j) { hhacc[m][j] = 0.f; xxacc[m][j] = 0.f; }

    gate_issue_chunk_nc(gb, row0, 0, tid);
    CPA_COMMIT();
    gate_issue_chunk_nc(gb + (uint32_t)BUF_W*4u, row0, 1, tid);
    CPA_COMMIT();

    for (int ck = 0; ck < 40; ++ck) {
        if (ck + 1 < 40) { CPA_WAIT(1); } else { CPA_WAIT(0); }
        __syncthreads();

        int buf = ck % 3;
        const uint32_t* Bh = gw + buf*BUF_W + 2*AH_W;
        const uint32_t* Bl = Bh + BH_W;
        uint32_t abase = gb + (uint32_t)(buf*BUF_W)*4u;

        #pragma unroll
        for (int ks = 0; ks < 2; ++ks) {
            int ko = kg*16 + ks*8;
            uint32_t ah = abase + ((mw*16 + lrow)*ASTR + ko + lcol)*4u;
            uint32_t a0h, a1h, a2h, a3h, a0l, a1l, a2l, a3l;
            ldsm4(a0h, a1h, a2h, a3h, ah);
            ldsm4(a0l, a1l, a2l, a3l, ah + AH_W*4u);
            #pragma unroll
            for (int nt = 0; nt < 5; ++nt) {
                int pb = (nt*8 + g)*ASTR + ko + tg;
                uint32_t b0h = Bh[pb], b1h = Bh[pb+4];
                uint32_t b0l = Bl[pb], b1l = Bl[pb+4];
                mma_bf16(hhacc[nt], a0h, a1h, a2h, a3h, b0h, b1h);
                mma_bf16(xxacc[nt], a0h, a1h, a2h, a3h, b0l, b1l);
                mma_bf16(xxacc[nt], a0l, a1l, a2l, a3l, b0h, b1h);
            }
        }
        __syncthreads();
        if (ck + 2 < 40) {
            gate_issue_chunk_nc(gb + (uint32_t)(((ck + 2) % 3) * BUF_W)*4u, row0, ck + 2, tid);
            CPA_COMMIT();
        }
    }

    float acc[5][4];
    #pragma unroll
    for (int m = 0; m < 5; ++m)
        #pragma unroll
        for (int j = 0; j < 4; ++j) acc[m][j] = hhacc[m][j] + xxacc[m][j];

    float* sRed = (float*)gw;
    if (kg == 1) {
        int base = (tid - 128) * 20;
        #pragma unroll
        for (int m = 0; m < 5; ++m)
            #pragma unroll
            for (int j = 0; j < 4; ++j) sRed[base + m*4 + j] = acc[m][j];
    }
    __syncthreads();
    if (kg == 0) {
        int base = tid * 20;
        #pragma unroll
        for (int m = 0; m < 5; ++m)
            #pragma unroll
            for (int j = 0; j < 4; ++j) acc[m][j] += sRed[base + m*4 + j];
    }
    __syncthreads();

    float* sL = (float*)(gw + 4096);
    if (kg == 0) {
        #pragma unroll
        for (int nt = 0; nt < 5; ++nt) {
            int col = nt*8 + tg*2;
            float b0 = __ldg(gate_b + col);
            float b1 = __ldg(gate_b + col + 1);
            sL[(mw*16 + g)*41 + col]         = acc[nt][0] + b0;
            sL[(mw*16 + g)*41 + col + 1]     = acc[nt][1] + b1;
            sL[(mw*16 + 8 + g)*41 + col]     = acc[nt][2] + b0;
            sL[(mw*16 + 8 + g)*41 + col + 1] = acc[nt][3] + b1;
        }
    }
    __syncthreads();

    if (tid < 64) {
        float* lp = sL + tid*41;
        float mx = -1e30f;
        #pragma unroll 8
        for (int n = 0; n < NF; ++n) mx = fmaxf(mx, lp[n]);
        float se = 0.f;
        #pragma unroll 8
        for (int n = 0; n < NF; ++n) se += expf(lp[n] - mx);
        float inv = 1.f / se;
        #pragma unroll 8
        for (int n = 0; n < NF; ++n) lp[n] = expf(lp[n] - mx) * inv;
    }
    __syncthreads();

    {
        int row = tid >> 2;
        int q   = tid & 3;
        int pb  = q * 8;
        const uint32_t* hh = g_HH + (size_t)(row0 + row)*1280 + pb;
        const uint32_t* hl = g_HL + (size_t)(row0 + row)*1280 + pb;
        const float* wp = sL + row*41;
        float2 a2[8];
        #pragma unroll
        for (int k = 0; k < 8; ++k) a2[k] = make_float2(0.f, 0.f);
        #pragma unroll 4
        for (int n = 0; n < NF; ++n) {
            float wv = wp[n];
            #pragma unroll
            for (int q4 = 0; q4 < 2; ++q4) {
                uint4 hv = *(const uint4*)(hh + n*32 + q4*4);
                uint4 lv = *(const uint4*)(hl + n*32 + q4*4);
                float2 f0 = rec2(hv.x, lv.x), f1 = rec2(hv.y, lv.y);
                float2 f2 = rec2(hv.z, lv.z), f3 = rec2(hv.w, lv.w);
                a2[q4*4+0].x += wv*f0.x; a2[q4*4+0].y += wv*f0.y;
                a2[q4*4+1].x += wv*f1.x; a2[q4*4+1].y += wv*f1.y;
                a2[q4*4+2].x += wv*f2.x; a2[q4*4+2].y += wv*f2.y;
                a2[q4*4+3].x += wv*f3.x; a2[q4*4+3].y += wv*f3.y;
            }
        }
        float* op = out + (size_t)(row0 + row)*64 + q*16;
        #pragma unroll
        for (int k = 0; k < 4; ++k)
            *(float4*)(op + k*4) = make_float4(a2[k*2].x, a2[k*2].y, a2[k*2+1].x, a2[k*2+1].y);
    }
}

// ---------------- launcher ------------------------------------------------
extern "C" void kernel_launch(void* const* d_in, const int* in_sizes, int n_in,
                              void* d_out, int out_size) {
    const float* x        = (const float*)d_in[0];
    const float* masker   = (const float*)d_in[1];
    const float* ln_gamma = (const float*)d_in[2];
    const float* ln_beta  = (const float*)d_in[3];
    const float* gnn_w    = (const float*)d_in[4];
    const float* gnn_b    = (const float*)d_in[5];
    const float* bn_gamma = (const float*)d_in[6];
    const float* bn_beta  = (const float*)d_in[7];
    const float* bn_mean  = (const float*)d_in[8];
    const float* bn_var   = (const float*)d_in[9];
    const float* gate_w   = (const float*)d_in[10];
    const float* gate_b   = (const float*)d_in[11];
    float* out = (float*)d_out;

    cudaFuncSetAttribute(k_forward, cudaFuncAttributeMaxDynamicSharedMemorySize,
                         SM_FWD_BYTES);
    cudaFuncSetAttribute(k_gate, cudaFuncAttributeMaxDynamicSharedMemorySize,
                         GSM_WORDS * (int)sizeof(uint32_t));

    prep_adj<<<2, 128>>>(masker, ln_gamma, ln_beta);
    prep_misc<<<312, 256>>>(bn_gamma, bn_beta, bn_mean, bn_var, gnn_w, gnn_b, gate_w);
    k_forward<<<BSZ / CHUNK, 256, SM_FWD_BYTES>>>(x);
    k_gate<<<BSZ * TT / 64, 256, GSM_WORDS * sizeof(uint32_t)>>>(gate_b, out);
}